// round 5
// baseline (speedup 1.0000x reference)
#include <cuda_runtime.h>
#include <math.h>
#include <stdint.h>

#define NN 8192
#define KK 32
#define NT 64                       // 8192/128 tiles per dim
#define NOFF (NT*(NT-1)/2)          // 2016 strictly-upper tiles
#define NPAIRS (NOFF + NT)          // 2080 softplus tiles
#define NAROW 64                    // A-scan: 64 row-tiles of 128
#define NACOL 16                    // 16 col-tiles of 512
#define NA (NAROW*NACOL)            // 1024 A-scan blocks
#define GRID (3*NA + 32)            // 3104: interleaved 2 pairs : 1 A

// dynamic smem layout sizes
#define SM_YS   0                   // A-path: Ys[512][33] floats
#define SM_XS   67584               // A-path: Xs[128][33]
#define SM_BIA  84480               // A-path: bI[128]
#define SM_BJA  84992               // A-path: bJ[512]
#define SM_RED  87040               // both:   red[16]
#define DYNSM   87552
// pairs-path layout (reuses front of the same buffer)
#define SM_XT   0                   // Xt[32][128]
#define SM_YT   16384               // Yt[32][128]
#define SM_BI   32768               // bI[128]
#define SM_BJ   33280               // bJ[128]

typedef unsigned long long u64;

#define FMA2(d,a,b,c) asm("fma.rn.f32x2 %0, %1, %2, %3;" : "=l"(d) : "l"(a), "l"(b), "l"(c))
#define PK2(d,lo,hi)  asm("mov.b64 %0, {%1, %2};" : "=l"(d) : "f"(lo), "f"(hi))
#define UPK2(lo,hi,s) asm("mov.b64 {%0, %1}, %2;" : "=f"(lo), "=f"(hi) : "l"(s))

// ---- scratch (no allocations allowed) ----
__device__ float  d_Wpart[64*KK*KK];
__device__ float  d_Spart[64*KK];
__device__ float  d_M [KK*KK];
__device__ float  d_Ya[KK*NN];          // 2a * M @ X
__device__ float  d_bv[NN];             // beta - a*q
__device__ double d_partSP[NPAIRS];
__device__ double d_partTA[NA];

// ---------- fused prep: softmax(X) chunk + exp(C) chunk + partial W,S ----------
__global__ void k_prep(const float* __restrict__ X, const float* __restrict__ C) {
    __shared__ float xs[KK][132];
    __shared__ float ec[KK][132];
    int blk = blockIdx.x, tid = threadIdx.x;
    int base = blk * 128;

    if (tid < 128) {
        int i = base + tid;
        float v[KK]; float s = 0.f;
#pragma unroll
        for (int p = 0; p < KK; p++) { v[p] = __expf(X[p*NN + i]); s += v[p]; }
        float inv = 1.f / s;
#pragma unroll
        for (int p = 0; p < KK; p++) xs[p][tid] = v[p] * inv;
    } else {
        int r = tid - 128;
        const float4* cp = (const float4*)&C[(base + r)*KK];
#pragma unroll
        for (int c4 = 0; c4 < 8; c4++) {
            float4 v = cp[c4];
            ec[c4*4+0][r] = __expf(v.x);
            ec[c4*4+1][r] = __expf(v.y);
            ec[c4*4+2][r] = __expf(v.z);
            ec[c4*4+3][r] = __expf(v.w);
        }
    }
    __syncthreads();

    if (tid < 32) {
        float s = 0.f;
#pragma unroll 8
        for (int r = 0; r < 128; r++) s += ec[tid][r];
        d_Spart[blk*32 + tid] = s;
    }

    int p = tid >> 3, k0 = (tid & 7) * 4;
    float a0 = 0.f, a1 = 0.f, a2 = 0.f, a3 = 0.f;
#pragma unroll 4
    for (int ii = 0; ii < 128; ii++) {
        float xv = xs[p][ii];
        a0 += xv * ec[k0+0][ii];
        a1 += xv * ec[k0+1][ii];
        a2 += xv * ec[k0+2][ii];
        a3 += xv * ec[k0+3][ii];
    }
    float* out = &d_Wpart[blk*1024 + p*32 + k0];
    out[0] = a0; out[1] = a1; out[2] = a2; out[3] = a3;
}

// ---------- fused: reduce partials, E = W/S, M = E^T E ----------
__global__ void k_wredM() {
    __shared__ float Es[KK*KK];
    __shared__ float Ssm[KK];
    int tid = threadIdx.x;
    float w[4];
#pragma unroll
    for (int c = 0; c < 4; c++) {
        int e = tid*4 + c;
        float s = 0.f;
#pragma unroll 8
        for (int b = 0; b < 64; b++) s += d_Wpart[b*1024 + e];
        w[c] = s;
    }
    if (tid < 32) {
        float s = 0.f;
#pragma unroll 8
        for (int b = 0; b < 64; b++) s += d_Spart[b*32 + tid];
        Ssm[tid] = s;
    }
    __syncthreads();
#pragma unroll
    for (int c = 0; c < 4; c++) {
        int e = tid*4 + c;
        Es[e] = w[c] / Ssm[e & 31];
    }
    __syncthreads();
#pragma unroll
    for (int c = 0; c < 4; c++) {
        int e = tid*4 + c;
        int p = e >> 5, q = e & 31;
        float s = 0.f;
#pragma unroll
        for (int r = 0; r < KK; r++) s += Es[r*KK + p] * Es[r*KK + q];
        d_M[e] = s;
    }
}

// ---------- Ya = 2a*M*X, b = beta - a*q ----------
__global__ void k_ya(const float* __restrict__ X, const float* __restrict__ beta,
                     const float* __restrict__ a_p) {
    __shared__ __align__(16) float Ms[KK][KK];
    __shared__ float qsm[4][32];
    int tid = threadIdx.x;
    int lane = tid & 31, w = tid >> 5;
    for (int idx = tid; idx < KK*KK; idx += 128)
        Ms[idx >> 5][idx & 31] = d_M[idx];
    __syncthreads();

    int i = blockIdx.x * 32 + lane;
    float a = a_p[0];
    float twoa = 2.f * a;
    float xv[KK];
#pragma unroll
    for (int q = 0; q < KK; q++) xv[q] = X[q*NN + i];

    float qp = 0.f;
#pragma unroll
    for (int pp = 0; pp < 8; pp++) {
        int p = w*8 + pp;
        const float4* mrow = (const float4*)&Ms[p][0];
        float tp = 0.f;
#pragma unroll
        for (int q4 = 0; q4 < 8; q4++) {
            float4 m = mrow[q4];
            tp += m.x * xv[q4*4+0] + m.y * xv[q4*4+1]
                + m.z * xv[q4*4+2] + m.w * xv[q4*4+3];
        }
        d_Ya[p*NN + i] = twoa * tp;
        qp += xv[p] * tp;
    }
    qsm[w][lane] = qp;
    __syncthreads();
    if (w == 0) {
        float qf = qsm[0][lane] + qsm[1][lane] + qsm[2][lane] + qsm[3][lane];
        d_bv[i] = beta[i] - a * qf;
    }
}

__device__ __forceinline__ float softplusf(float x) {
    return fmaxf(x, 0.f) + __logf(1.f + __expf(-fabsf(x)));
}

// ================= fused main kernel: pairs-softplus tiles + A-scan blocks ===========

// ---- pairs path: softplus over one 128x128 tile, NO A access ----
__device__ __forceinline__ void pairs_path(int pid, const float* __restrict__ X,
                                           char* sm, int tid, int slot) {
    float (*Xt)[128] = (float(*)[128])(sm + SM_XT);
    float (*Yt)[128] = (float(*)[128])(sm + SM_YT);
    float* bI  = (float*)(sm + SM_BI);
    float* bJ  = (float*)(sm + SM_BJ);
    float* red = (float*)(sm + SM_RED);

    int I, J;
    if (pid < NOFF) {
        int rem = pid, rl = NT - 1; I = 0;
        while (rem >= rl) { rem -= rl; rl--; I++; }
        J = I + 1 + rem;
    } else {
        I = pid - NOFF; J = I;
    }
    int iBase = I * 128, jBase = J * 128;

#pragma unroll
    for (int c = 0; c < 4; c++) {
        int e = c*1024 + tid*4;
        int p = e >> 7, ii = e & 127;
        *(float4*)&Xt[p][ii] = *(const float4*)&X   [p*NN + iBase + ii];
        *(float4*)&Yt[p][ii] = *(const float4*)&d_Ya[p*NN + jBase + ii];
    }
    if (tid < 128) bI[tid] = d_bv[iBase + tid];
    else           bJ[tid - 128] = d_bv[jBase + tid - 128];
    __syncthreads();

    int tx = tid & 15, ty = tid >> 4;
    float bIr[8], bJc[8];
#pragma unroll
    for (int r = 0; r < 8; r++) bIr[r] = bI[ty*8 + r];
#pragma unroll
    for (int c = 0; c < 4; c++) { bJc[c] = bJ[tx*4 + c]; bJc[c+4] = bJ[64 + tx*4 + c]; }

    u64 acc2[8][4];
#pragma unroll
    for (int r = 0; r < 8; r++)
#pragma unroll
        for (int cp = 0; cp < 4; cp++)
            PK2(acc2[r][cp], bIr[r] + bJc[2*cp], bIr[r] + bJc[2*cp + 1]);

#pragma unroll
    for (int k = 0; k < KK; k++) {
        float4 xa = *(float4*)&Xt[k][ty*8];
        float4 xb = *(float4*)&Xt[k][ty*8 + 4];
        const u64* yp0 = (const u64*)&Yt[k][tx*4];
        const u64* yp1 = (const u64*)&Yt[k][64 + tx*4];
        u64 y2[4] = {yp0[0], yp0[1], yp1[0], yp1[1]};
        float xf[8] = {xa.x, xa.y, xa.z, xa.w, xb.x, xb.y, xb.z, xb.w};
#pragma unroll
        for (int r = 0; r < 8; r++) {
            u64 xx;
            PK2(xx, xf[r], xf[r]);
#pragma unroll
            for (int cp = 0; cp < 4; cp++)
                FMA2(acc2[r][cp], xx, y2[cp], acc2[r][cp]);
        }
    }

    float sSP = 0.f;
    if (I != J) {
#pragma unroll
        for (int r = 0; r < 8; r++)
#pragma unroll
            for (int cp = 0; cp < 4; cp++) {
                float t0, t1;
                UPK2(t0, t1, acc2[r][cp]);
                sSP += softplusf(t0) + softplusf(t1);
            }
        sSP *= 2.f;
    } else {
#pragma unroll
        for (int r = 0; r < 8; r++) {
            int gi = iBase + ty*8 + r;
#pragma unroll
            for (int c = 0; c < 8; c++) {
                int gj = jBase + ((c < 4) ? (tx*4 + c) : (64 + tx*4 + (c - 4)));
                float t0, t1;
                UPK2(t0, t1, acc2[r][c >> 1]);
                float th = (c & 1) ? t1 : t0;
                if (gi < gj) sSP += 2.f * softplusf(th);
            }
        }
    }

#pragma unroll
    for (int o = 16; o > 0; o >>= 1)
        sSP += __shfl_xor_sync(0xffffffffu, sSP, o);
    int wid = tid >> 5, lane = tid & 31;
    if (lane == 0) red[wid] = sSP;
    __syncthreads();
    if (tid == 0) {
        float s1 = 0.f;
#pragma unroll
        for (int w = 0; w < 8; w++) s1 += red[w];
        d_partSP[slot] = (double)s1;
    }
}

// ---- A path: stream a 128x512 block of A, accumulate sum A_ij*(b_i+b_j+x_i.y_j) ----
#define HITLOOP(m, base, sub)                                   \
    while (m) {                                                 \
        int b = __ffs(m) - 1; m &= m - 1;                       \
        int col = (base) + 4*b + (sub);                         \
        s += xk * Ys[col*33 + lane];                            \
        if (lane == 0) sb += bJa[col];                          \
    }

#define PROCESS4(v, base)                                                  \
    {                                                                      \
        unsigned m0 = __ballot_sync(0xffffffffu, (v).x != 0.f);            \
        unsigned m1 = __ballot_sync(0xffffffffu, (v).y != 0.f);            \
        unsigned m2 = __ballot_sync(0xffffffffu, (v).z != 0.f);            \
        unsigned m3 = __ballot_sync(0xffffffffu, (v).w != 0.f);            \
        h += __popc(m0) + __popc(m1) + __popc(m2) + __popc(m3);            \
        HITLOOP(m0, base, 0); HITLOOP(m1, base, 1);                        \
        HITLOOP(m2, base, 2); HITLOOP(m3, base, 3);                        \
    }

__device__ __forceinline__ void a_path(int aid, const float* __restrict__ X,
                                       const float* __restrict__ A,
                                       char* sm, int tid) {
    float* Ys  = (float*)(sm + SM_YS);    // [512][33]
    float* Xs  = (float*)(sm + SM_XS);    // [128][33]
    float* bIa = (float*)(sm + SM_BIA);
    float* bJa = (float*)(sm + SM_BJA);
    float* red = (float*)(sm + SM_RED);

    int rowT = aid >> 4, colT = aid & 15;
    int iB = rowT * 128, jB = colT * 512;

    for (int idx = tid; idx < 128*32; idx += 256) {
        int k = idx >> 7, i = idx & 127;
        Xs[i*33 + k] = X[k*NN + iB + i];
    }
    for (int idx = tid; idx < 512*32; idx += 256) {
        int k = idx >> 9, c = idx & 511;
        Ys[c*33 + k] = d_Ya[k*NN + jB + c];
    }
    if (tid < 128) bIa[tid] = d_bv[iB + tid];
    for (int idx = tid; idx < 512; idx += 256) bJa[idx] = d_bv[jB + idx];
    __syncthreads();

    int w = tid >> 5, lane = tid & 31;
    float s = 0.f, sb = 0.f;

    for (int rr = 0; rr < 16; rr++) {
        int row = w*16 + rr;
        float xk  = Xs[row*33 + lane];
        float bIv = bIa[row];
        const float4* arow = (const float4*)&A[(u64)(iB + row)*NN + jB];
        float4 v0 = __ldcs(&arow[       lane]);
        float4 v1 = __ldcs(&arow[ 32 + lane]);
        float4 v2 = __ldcs(&arow[ 64 + lane]);
        float4 v3 = __ldcs(&arow[ 96 + lane]);
        int h = 0;
        PROCESS4(v0, 0);
        PROCESS4(v1, 128);
        PROCESS4(v2, 256);
        PROCESS4(v3, 384);
        if (lane == 0) sb += bIv * (float)h;
    }
    if (lane == 0) s += sb;

#pragma unroll
    for (int o = 16; o > 0; o >>= 1)
        s += __shfl_xor_sync(0xffffffffu, s, o);
    if (lane == 0) red[w] = s;
    __syncthreads();
    if (tid == 0) {
        float t = 0.f;
#pragma unroll
        for (int ww = 0; ww < 8; ww++) t += red[ww];
        d_partTA[aid] = (double)t;
    }
}

__global__ void __launch_bounds__(256, 2)
k_main(const float* __restrict__ X, const float* __restrict__ A) {
    extern __shared__ char sm[];
    int bid = blockIdx.x, tid = threadIdx.x;

    if (bid < 3*NA) {
        int g = bid / 3, r = bid - 3*g;
        if (r == 1) { a_path(g, X, A, sm, tid); return; }
        int pid = 2*g + (r == 2 ? 1 : 0);
        pairs_path(pid, X, sm, tid, pid);
    } else {
        int pid = 2*NA + (bid - 3*NA);
        pairs_path(pid, X, sm, tid, pid);
    }
}

// ---------- deterministic final reduction ----------
__global__ void k_final(float* __restrict__ out) {
    __shared__ double rSP[256], rTA[256];
    int t = threadIdx.x;
    double s1 = 0.0, s2 = 0.0;
    for (int i = t; i < NPAIRS; i += 256) s1 += d_partSP[i];
    for (int i = t; i < NA; i += 256)     s2 += d_partTA[i];
    rSP[t] = s1; rTA[t] = s2; __syncthreads();
    for (int s = 128; s > 0; s >>= 1) {
        if (t < s) { rSP[t] += rSP[t+s]; rTA[t] += rTA[t+s]; }
        __syncthreads();
    }
    if (t == 0) out[0] = (float)(0.5 * rTA[0] - 0.5 * rSP[0]);
}

extern "C" void kernel_launch(void* const* d_in, const int* in_sizes, int n_in,
                              void* d_out, int out_size) {
    const float* A    = (const float*)d_in[0];
    const float* beta = (const float*)d_in[1];
    const float* a    = (const float*)d_in[2];
    const float* X    = (const float*)d_in[3];
    const float* C    = (const float*)d_in[4];
    float* out = (float*)d_out;

    cudaFuncSetAttribute(k_main, cudaFuncAttributeMaxDynamicSharedMemorySize, DYNSM);

    k_prep<<<64, 256>>>(X, C);                 // 1
    k_wredM<<<1, 256>>>();                     // 2
    k_ya<<<NN/32, 128>>>(X, beta, a);          // 3
    k_main<<<GRID, 256, DYNSM>>>(X, A);        // 4  <- profiled slot
    k_final<<<1, 256>>>(out);                  // 5
}

// round 6
// speedup vs baseline: 1.5154x; 1.5154x over previous
#include <cuda_runtime.h>
#include <math.h>
#include <stdint.h>

#define NN 8192
#define KK 32
#define NT 64                       // 8192/128 tiles per dim
#define NOFF (NT*(NT-1)/2)          // 2016 strictly-upper tiles
#define NTILES (NOFF + NT)          // 2080 tiles total

typedef unsigned long long u64;

#define FMA2(d,a,b,c) asm("fma.rn.f32x2 %0, %1, %2, %3;" : "=l"(d) : "l"(a), "l"(b), "l"(c))
#define PK2(d,lo,hi)  asm("mov.b64 %0, {%1, %2};" : "=l"(d) : "f"(lo), "f"(hi))
#define UPK2(lo,hi,s) asm("mov.b64 {%0, %1}, %2;" : "=f"(lo), "=f"(hi) : "l"(s))
#define CPA16(dst,src) asm volatile("cp.async.cg.shared.global [%0], [%1], 16;" :: "r"(dst), "l"(src))

// smem layout (bytes)
#define SM_XT   0                   // Xt[32][128]           16384
#define SM_YT   16384               // Yt[32][128]           16384
#define SM_ADIR 32768               // Adir[128][128] 512B/row  65536
#define SM_ATRP 98304               // Atrp[128][132] 528B/row  67584
#define SM_BI   165888              // 512
#define SM_BJ   166400              // 512
#define SM_RED  166912              // 64
#define PAIR_SMEM 166976

// ---- scratch (no allocations allowed) ----
__device__ float  d_Wpart[64*KK*KK];
__device__ float  d_Spart[64*KK];
__device__ float  d_M [KK*KK];
__device__ float  d_Ya[KK*NN];          // 2a * M @ X
__device__ float  d_bv[NN];             // beta - a*q
__device__ double d_partSP[NTILES];
__device__ double d_partTA[NTILES];

// ---------- fused prep: softmax(X) chunk + exp(C) chunk + partial W,S ----------
__global__ void k_prep(const float* __restrict__ X, const float* __restrict__ C) {
    __shared__ float xs[KK][132];
    __shared__ float ec[KK][132];
    int blk = blockIdx.x, tid = threadIdx.x;
    int base = blk * 128;

    if (tid < 128) {
        int i = base + tid;
        float v[KK]; float s = 0.f;
#pragma unroll
        for (int p = 0; p < KK; p++) { v[p] = __expf(X[p*NN + i]); s += v[p]; }
        float inv = 1.f / s;
#pragma unroll
        for (int p = 0; p < KK; p++) xs[p][tid] = v[p] * inv;
    } else {
        int r = tid - 128;
        const float4* cp = (const float4*)&C[(base + r)*KK];
#pragma unroll
        for (int c4 = 0; c4 < 8; c4++) {
            float4 v = cp[c4];
            ec[c4*4+0][r] = __expf(v.x);
            ec[c4*4+1][r] = __expf(v.y);
            ec[c4*4+2][r] = __expf(v.z);
            ec[c4*4+3][r] = __expf(v.w);
        }
    }
    __syncthreads();

    if (tid < 32) {
        float s = 0.f;
#pragma unroll 8
        for (int r = 0; r < 128; r++) s += ec[tid][r];
        d_Spart[blk*32 + tid] = s;
    }

    int p = tid >> 3, k0 = (tid & 7) * 4;
    float a0 = 0.f, a1 = 0.f, a2 = 0.f, a3 = 0.f;
#pragma unroll 4
    for (int ii = 0; ii < 128; ii++) {
        float xv = xs[p][ii];
        a0 += xv * ec[k0+0][ii];
        a1 += xv * ec[k0+1][ii];
        a2 += xv * ec[k0+2][ii];
        a3 += xv * ec[k0+3][ii];
    }
    float* out = &d_Wpart[blk*1024 + p*32 + k0];
    out[0] = a0; out[1] = a1; out[2] = a2; out[3] = a3;
}

// ---------- fused: reduce partials, E = W/S, M = E^T E ----------
__global__ void k_wredM() {
    __shared__ float Es[KK*KK];
    __shared__ float Ssm[KK];
    int tid = threadIdx.x;
    float w[4];
#pragma unroll
    for (int c = 0; c < 4; c++) {
        int e = tid*4 + c;
        float s = 0.f;
#pragma unroll 8
        for (int b = 0; b < 64; b++) s += d_Wpart[b*1024 + e];
        w[c] = s;
    }
    if (tid < 32) {
        float s = 0.f;
#pragma unroll 8
        for (int b = 0; b < 64; b++) s += d_Spart[b*32 + tid];
        Ssm[tid] = s;
    }
    __syncthreads();
#pragma unroll
    for (int c = 0; c < 4; c++) {
        int e = tid*4 + c;
        Es[e] = w[c] / Ssm[e & 31];
    }
    __syncthreads();
#pragma unroll
    for (int c = 0; c < 4; c++) {
        int e = tid*4 + c;
        int p = e >> 5, q = e & 31;
        float s = 0.f;
#pragma unroll
        for (int r = 0; r < KK; r++) s += Es[r*KK + p] * Es[r*KK + q];
        d_M[e] = s;
    }
}

// ---------- Ya = 2a*M*X, b = beta - a*q : 8 warps split p, X staged in smem ----------
__global__ void k_ya(const float* __restrict__ X, const float* __restrict__ beta,
                     const float* __restrict__ a_p) {
    __shared__ __align__(16) float Ms[KK][KK];
    __shared__ float Xw[KK][33];
    __shared__ float qsm[8][32];
    int tid = threadIdx.x;
    int lane = tid & 31, w = tid >> 5;
    int cbase = blockIdx.x * 32;

#pragma unroll
    for (int c = 0; c < 4; c++) {
        int idx = c*256 + tid;
        Ms[idx >> 5][idx & 31] = d_M[idx];
    }
#pragma unroll
    for (int c = 0; c < 4; c++) {
        int idx = c*256 + tid;
        int q = idx >> 5, col = idx & 31;
        Xw[q][col] = X[q*NN + cbase + col];
    }
    __syncthreads();

    float a = a_p[0];
    float twoa = 2.f * a;
    float xv[KK];
#pragma unroll
    for (int q = 0; q < KK; q++) xv[q] = Xw[q][lane];

    int i = cbase + lane;
    float qp = 0.f;
#pragma unroll
    for (int pp = 0; pp < 4; pp++) {
        int p = w*4 + pp;
        const float4* mrow = (const float4*)&Ms[p][0];
        float tp = 0.f;
#pragma unroll
        for (int q4 = 0; q4 < 8; q4++) {
            float4 m = mrow[q4];
            tp += m.x * xv[q4*4+0] + m.y * xv[q4*4+1]
                + m.z * xv[q4*4+2] + m.w * xv[q4*4+3];
        }
        d_Ya[p*NN + i] = twoa * tp;
        qp += xv[p] * tp;
    }
    qsm[w][lane] = qp;
    __syncthreads();
    if (w == 0) {
        float qf = 0.f;
#pragma unroll
        for (int ww = 0; ww < 8; ww++) qf += qsm[ww][lane];
        d_bv[i] = beta[i] - a * qf;
    }
}

__device__ __forceinline__ float softplusf(float x) {
    return fmaxf(x, 0.f) + __logf(1.f + __expf(-fabsf(x)));
}

// ---------- unified pair kernel: one 128x128 tile per block, A fully staged ----------
__global__ void __launch_bounds__(256, 1)
k_pairs(const float* __restrict__ X, const float* __restrict__ A) {
    extern __shared__ char sm[];
    float (*Xt)[128]   = (float(*)[128])(sm + SM_XT);
    float (*Yt)[128]   = (float(*)[128])(sm + SM_YT);
    float (*Adir)[128] = (float(*)[128])(sm + SM_ADIR);
    float (*Atrp)[132] = (float(*)[132])(sm + SM_ATRP);
    float* bI  = (float*)(sm + SM_BI);
    float* bJ  = (float*)(sm + SM_BJ);
    float* red = (float*)(sm + SM_RED);

    int pid = blockIdx.x, tid = threadIdx.x;
    int I, J;
    bool isDiag;
    if (pid < NOFF) {
        int rem = pid, rl = NT - 1; I = 0;
        while (rem >= rl) { rem -= rl; rl--; I++; }
        J = I + 1 + rem;
        isDiag = false;
    } else {
        I = pid - NOFF; J = I;
        isDiag = true;
    }
    int iBase = I * 128, jBase = J * 128;

    // ---- stage A blocks via cp.async (overlapped with mainloop) ----
    {
        uint32_t adir = (uint32_t)__cvta_generic_to_shared(&Adir[0][0]);
#pragma unroll
        for (int c = 0; c < 16; c++) {
            int idx = c*256 + tid;
            int row = idx >> 5, c16 = idx & 31;
            CPA16(adir + row*512 + c16*16,
                  &A[(u64)(iBase + row)*NN + jBase + c16*4]);
        }
        if (!isDiag) {
            uint32_t atrp = (uint32_t)__cvta_generic_to_shared(&Atrp[0][0]);
#pragma unroll
            for (int c = 0; c < 16; c++) {
                int idx = c*256 + tid;
                int row = idx >> 5, c16 = idx & 31;
                CPA16(atrp + row*528 + c16*16,
                      &A[(u64)(jBase + row)*NN + iBase + c16*4]);
            }
        }
        asm volatile("cp.async.commit_group;" ::: "memory");
    }

    // ---- stage X/Ya tiles + biases ----
#pragma unroll
    for (int c = 0; c < 4; c++) {
        int e = c*1024 + tid*4;
        int p = e >> 7, ii = e & 127;
        *(float4*)&Xt[p][ii] = *(const float4*)&X   [p*NN + iBase + ii];
        *(float4*)&Yt[p][ii] = *(const float4*)&d_Ya[p*NN + jBase + ii];
    }
    if (tid < 128) bI[tid] = d_bv[iBase + tid];
    else           bJ[tid - 128] = d_bv[jBase + tid - 128];
    __syncthreads();

    int tx = tid & 15, ty = tid >> 4;
    float bIr[8], bJc[8];
#pragma unroll
    for (int r = 0; r < 8; r++) bIr[r] = bI[ty*8 + r];
#pragma unroll
    for (int c = 0; c < 4; c++) { bJc[c] = bJ[tx*4 + c]; bJc[c+4] = bJ[64 + tx*4 + c]; }

    u64 acc2[8][4];
#pragma unroll
    for (int r = 0; r < 8; r++)
#pragma unroll
        for (int cp = 0; cp < 4; cp++)
            PK2(acc2[r][cp], bIr[r] + bJc[2*cp], bIr[r] + bJc[2*cp + 1]);

    // ---- FFMA2 mainloop (A stream arrives underneath) ----
#pragma unroll
    for (int k = 0; k < KK; k++) {
        float4 xa = *(float4*)&Xt[k][ty*8];
        float4 xb = *(float4*)&Xt[k][ty*8 + 4];
        const u64* yp0 = (const u64*)&Yt[k][tx*4];
        const u64* yp1 = (const u64*)&Yt[k][64 + tx*4];
        u64 y2[4] = {yp0[0], yp0[1], yp1[0], yp1[1]};
        float xf[8] = {xa.x, xa.y, xa.z, xa.w, xb.x, xb.y, xb.z, xb.w};
#pragma unroll
        for (int r = 0; r < 8; r++) {
            u64 xx;
            PK2(xx, xf[r], xf[r]);
#pragma unroll
            for (int cp = 0; cp < 4; cp++)
                FMA2(acc2[r][cp], xx, y2[cp], acc2[r][cp]);
        }
    }
    // acc2 holds theta

    // ---- softplus (no A dependence) BEFORE the cp.async wait ----
    float sSP = 0.f;
    if (!isDiag) {
#pragma unroll
        for (int r = 0; r < 8; r++)
#pragma unroll
            for (int cp = 0; cp < 4; cp++) {
                float t0, t1;
                UPK2(t0, t1, acc2[r][cp]);
                sSP += softplusf(t0) + softplusf(t1);
            }
        sSP *= 2.f;
    } else {
#pragma unroll
        for (int r = 0; r < 8; r++) {
            int gi = ty*8 + r;
#pragma unroll
            for (int c = 0; c < 8; c++) {
                int gj = (c < 4) ? (tx*4 + c) : (64 + tx*4 + (c - 4));
                float t0, t1;
                UPK2(t0, t1, acc2[r][c >> 1]);
                float th = (c & 1) ? t1 : t0;
                if (gi < gj) sSP += 2.f * softplusf(th);
            }
        }
    }

    // ---- wait for A, then theta.A entirely from smem ----
    asm volatile("cp.async.wait_group 0;" ::: "memory");
    __syncthreads();

    float sTA = 0.f;
    u64 sTA2; PK2(sTA2, 0.f, 0.f);

    // direct block: sum over all 64 elements (valid for diag too)
#pragma unroll
    for (int r = 0; r < 8; r++) {
        int row = ty*8 + r;
        const u64* ap0 = (const u64*)&Adir[row][tx*4];
        const u64* ap1 = (const u64*)&Adir[row][64 + tx*4];
        u64 a2[4] = {ap0[0], ap0[1], ap1[0], ap1[1]};
#pragma unroll
        for (int cp = 0; cp < 4; cp++)
            FMA2(sTA2, acc2[r][cp], a2[cp], sTA2);
    }

    if (!isDiag) {
        // transposed block: A[j][i] against theta[r][c]
        float sT0 = 0.f, sT1 = 0.f;
#pragma unroll
        for (int c = 0; c < 8; c++) {
            int rowp = (c < 4) ? (tx*4 + c) : (64 + tx*4 + (c - 4));
            float4 b0 = *(const float4*)&Atrp[rowp][ty*8];
            float4 b1 = *(const float4*)&Atrp[rowp][ty*8 + 4];
            float atv[8] = {b0.x, b0.y, b0.z, b0.w, b1.x, b1.y, b1.z, b1.w};
            int cp = c >> 1;
            float acc = 0.f;
#pragma unroll
            for (int r = 0; r < 8; r++) {
                float t0, t1;
                UPK2(t0, t1, acc2[r][cp]);
                acc += ((c & 1) ? t1 : t0) * atv[r];
            }
            if (c & 1) sT1 += acc; else sT0 += acc;
        }
        sTA += sT0 + sT1;
    }

    {
        float t0, t1;
        UPK2(t0, t1, sTA2);
        sTA += t0 + t1;
    }

    // ---- deterministic block reduction ----
#pragma unroll
    for (int o = 16; o > 0; o >>= 1) {
        sSP += __shfl_xor_sync(0xffffffffu, sSP, o);
        sTA += __shfl_xor_sync(0xffffffffu, sTA, o);
    }
    int wid = tid >> 5, lane = tid & 31;
    if (lane == 0) { red[wid] = sSP; red[8 + wid] = sTA; }
    __syncthreads();
    if (tid == 0) {
        float s1 = 0.f, s2 = 0.f;
#pragma unroll
        for (int w = 0; w < 8; w++) { s1 += red[w]; s2 += red[8 + w]; }
        d_partSP[pid] = (double)s1;
        d_partTA[pid] = (double)s2;
    }
}

// ---------- deterministic final reduction ----------
__global__ void k_final(float* __restrict__ out) {
    __shared__ double rSP[256], rTA[256];
    int t = threadIdx.x;
    double s1 = 0.0, s2 = 0.0;
    for (int i = t; i < NTILES; i += 256) { s1 += d_partSP[i]; s2 += d_partTA[i]; }
    rSP[t] = s1; rTA[t] = s2; __syncthreads();
    for (int s = 128; s > 0; s >>= 1) {
        if (t < s) { rSP[t] += rSP[t+s]; rTA[t] += rTA[t+s]; }
        __syncthreads();
    }
    if (t == 0) out[0] = (float)(0.5 * rTA[0] - 0.5 * rSP[0]);
}

extern "C" void kernel_launch(void* const* d_in, const int* in_sizes, int n_in,
                              void* d_out, int out_size) {
    const float* A    = (const float*)d_in[0];
    const float* beta = (const float*)d_in[1];
    const float* a    = (const float*)d_in[2];
    const float* X    = (const float*)d_in[3];
    const float* C    = (const float*)d_in[4];
    float* out = (float*)d_out;

    cudaFuncSetAttribute(k_pairs, cudaFuncAttributeMaxDynamicSharedMemorySize, PAIR_SMEM);

    k_prep<<<64, 256>>>(X, C);                       // 1
    k_wredM<<<1, 256>>>();                           // 2
    k_ya<<<NN/32, 256>>>(X, beta, a);                // 3
    k_pairs<<<NTILES, 256, PAIR_SMEM>>>(X, A);       // 4  <- profiled slot
    k_final<<<1, 256>>>(out);                        // 5
}